// round 1
// baseline (speedup 1.0000x reference)
#include <cuda_runtime.h>

#define NN 50000
#define NE 800000
#define DD 128

// Scratch (static __device__ arrays: allocation-free)
static __device__ float g_agg[(size_t)NN * DD];
static __device__ float g_x1 [(size_t)NN * DD];
static __device__ float g_x2 [(size_t)NN * DD];
static __device__ float g_invdeg[NN];
static __device__ int   g_deg[NN];
static __device__ float g_B[256 * DD];   // fused [Wl;Wr] transposed to [K=256][N=128]

// ---------------- degree kernels ----------------
__global__ void k_zero_deg() {
    int i = blockIdx.x * blockDim.x + threadIdx.x;
    if (i < NN) g_deg[i] = 0;
}
__global__ void k_count_deg(const int* __restrict__ row) {
    int e = blockIdx.x * blockDim.x + threadIdx.x;
    if (e < NE) atomicAdd(&g_deg[row[e]], 1);
}
__global__ void k_invdeg() {
    int i = blockIdx.x * blockDim.x + threadIdx.x;
    if (i < NN) g_invdeg[i] = 1.0f / fmaxf((float)g_deg[i], 1.0f);
}

// ---------------- zero agg ----------------
__global__ void k_zero_agg() {
    int i = blockIdx.x * blockDim.x + threadIdx.x;   // NN*DD/4 = 1.6M float4
    if (i < NN * DD / 4)
        ((float4*)g_agg)[i] = make_float4(0.f, 0.f, 0.f, 0.f);
}

// ---------------- edge scatter: agg[row] += maybe_relu(src[col]) ----------------
// One warp per edge: 32 lanes x float4 = 512B contiguous row.
template <bool RELU>
__global__ void k_scatter(const float* __restrict__ src,
                          const int* __restrict__ row,
                          const int* __restrict__ col) {
    unsigned idx  = blockIdx.x * blockDim.x + threadIdx.x;
    unsigned e    = idx >> 5u;
    unsigned lane = idx & 31u;
    if (e >= NE) return;
    int c = __ldg(col + e);
    int r = __ldg(row + e);
    float4 v = __ldg((const float4*)(src + (size_t)c * DD) + lane);
    if (RELU) {
        v.x = fmaxf(v.x, 0.f); v.y = fmaxf(v.y, 0.f);
        v.z = fmaxf(v.z, 0.f); v.w = fmaxf(v.w, 0.f);
    }
    float* d = g_agg + (size_t)r * DD + lane * 4u;
    asm volatile("red.global.add.v4.f32 [%0], {%1,%2,%3,%4};"
                 :: "l"(d), "f"(v.x), "f"(v.y), "f"(v.z), "f"(v.w)
                 : "memory");
}

// ---------------- build fused weight matrix B[k][j] ----------------
// k<128 -> Wl[j][k] ; k>=128 -> Wr[j][k-128]    (W given row-major [out=128][in=128])
__global__ void k_buildB(const float* __restrict__ Wl, const float* __restrict__ Wr) {
    int idx = blockIdx.x * blockDim.x + threadIdx.x;   // 0 .. 256*128
    if (idx >= 256 * DD) return;
    int k = idx >> 7, j = idx & 127;
    g_B[idx] = (k < 128) ? Wl[j * DD + k] : Wr[j * DD + (k - 128)];
}

// ---------------- fused SAGE GEMM ----------------
// out[i][j] = sum_k A[i][k] * B[k][j] + bias[j] (+ h[i][j] if RES)
//   A[i][k<128]  = agg[i][k] * invdeg[i]
//   A[i][k>=128] = maybe_relu(h[i][k-128])
// M=50000, N=128, K=256. CTA tile 128x128, 256 threads, 8x8 per thread, BK=16.
template <bool RELU, bool RES>
__global__ void __launch_bounds__(256)
k_gemm(const float* __restrict__ h, const float* __restrict__ bias,
       float* __restrict__ out) {
    __shared__ float As[16 * 132];   // [kk][i], padded stride 132
    __shared__ float Bs[16 * 132];   // [kk][j], padded stride 132
    __shared__ float invd[128];
    __shared__ float bsh[128];

    const int t = threadIdx.x;
    const int rowBase = blockIdx.x * 128;
    if (t < 128) {
        int gi = rowBase + t;
        invd[t] = (gi < NN) ? g_invdeg[gi] : 0.f;
        bsh[t]  = bias[t];
    }
    __syncthreads();

    const int tx = t & 15;   // col group
    const int ty = t >> 4;   // row group

    float acc[8][8];
#pragma unroll
    for (int r = 0; r < 8; r++)
#pragma unroll
        for (int c = 0; c < 8; c++) acc[r][c] = 0.f;

    for (int k0 = 0; k0 < 256; k0 += 16) {
        // ---- load A tile (transposed into smem) ----
#pragma unroll
        for (int u = 0; u < 2; u++) {
            int cIdx = t + u * 256;            // 0..511
            int i = cIdx >> 2, q = cIdx & 3;   // row-in-tile, float4-within-16k
            int gi = rowBase + i;
            int k = k0 + q * 4;
            float4 v = make_float4(0.f, 0.f, 0.f, 0.f);
            if (gi < NN) {
                if (k0 < 128) {
                    v = __ldg((const float4*)(g_agg + (size_t)gi * DD + k));
                    float s = invd[i];
                    v.x *= s; v.y *= s; v.z *= s; v.w *= s;
                } else {
                    v = __ldg((const float4*)(h + (size_t)gi * DD + (k - 128)));
                    if (RELU) {
                        v.x = fmaxf(v.x, 0.f); v.y = fmaxf(v.y, 0.f);
                        v.z = fmaxf(v.z, 0.f); v.w = fmaxf(v.w, 0.f);
                    }
                }
            }
            As[(q * 4 + 0) * 132 + i] = v.x;
            As[(q * 4 + 1) * 132 + i] = v.y;
            As[(q * 4 + 2) * 132 + i] = v.z;
            As[(q * 4 + 3) * 132 + i] = v.w;
        }
        // ---- load B tile ----
#pragma unroll
        for (int u = 0; u < 2; u++) {
            int cIdx = t + u * 256;            // 0..511
            int kk = cIdx >> 5, f = cIdx & 31; // 16 rows x 32 float4
            float4 v = __ldg((const float4*)(g_B + (k0 + kk) * DD + f * 4));
            *(float4*)(Bs + kk * 132 + f * 4) = v;
        }
        __syncthreads();

        // ---- compute ----
#pragma unroll
        for (int kk = 0; kk < 16; kk++) {
            float a[8], b[8];
            *(float4*)(a)     = *(const float4*)(As + kk * 132 + ty * 8);
            *(float4*)(a + 4) = *(const float4*)(As + kk * 132 + ty * 8 + 4);
            *(float4*)(b)     = *(const float4*)(Bs + kk * 132 + tx * 8);
            *(float4*)(b + 4) = *(const float4*)(Bs + kk * 132 + tx * 8 + 4);
#pragma unroll
            for (int r = 0; r < 8; r++)
#pragma unroll
                for (int c = 0; c < 8; c++)
                    acc[r][c] += a[r] * b[c];
        }
        __syncthreads();
    }

    // ---- epilogue: bias (+ residual), store ----
#pragma unroll
    for (int r = 0; r < 8; r++) {
        int gi = rowBase + ty * 8 + r;
        if (gi >= NN) continue;
#pragma unroll
        for (int c = 0; c < 8; c += 4) {
            int j = tx * 8 + c;
            float4 o;
            o.x = acc[r][c]     + bsh[j];
            o.y = acc[r][c + 1] + bsh[j + 1];
            o.z = acc[r][c + 2] + bsh[j + 2];
            o.w = acc[r][c + 3] + bsh[j + 3];
            if (RES) {
                float4 xv = __ldg((const float4*)(h + (size_t)gi * DD + j));
                o.x += xv.x; o.y += xv.y; o.z += xv.z; o.w += xv.w;
            }
            *(float4*)(out + (size_t)gi * DD + j) = o;
        }
    }
}

// ---------------- launch ----------------
extern "C" void kernel_launch(void* const* d_in, const int* in_sizes, int n_in,
                              void* d_out, int out_size) {
    const float* x    = (const float*)d_in[0];
    const int*   erow = (const int*)  d_in[1];
    const int*   ecol = (const int*)  d_in[2];
    const float* Wl0 = (const float*)d_in[3];
    const float* Wr0 = (const float*)d_in[4];
    const float* b0  = (const float*)d_in[5];
    const float* Wl1 = (const float*)d_in[6];
    const float* Wr1 = (const float*)d_in[7];
    const float* b1  = (const float*)d_in[8];
    const float* Wl2 = (const float*)d_in[9];
    const float* Wr2 = (const float*)d_in[10];
    const float* b2  = (const float*)d_in[11];
    float* out = (float*)d_out;

    float *p_x1 = nullptr, *p_x2 = nullptr;
    cudaGetSymbolAddress((void**)&p_x1, g_x1);
    cudaGetSymbolAddress((void**)&p_x2, g_x2);

    const int nodeBlocks = (NN + 255) / 256;
    const int edgeBlocks = (NE + 255) / 256;
    const int scatBlocks = (NE * 32 + 255) / 256;   // 100000
    const int zeroBlocks = (NN * DD / 4 + 255) / 256;
    const int gemmBlocks = (NN + 127) / 128;        // 391

    // degrees (same for every layer)
    k_zero_deg<<<nodeBlocks, 256>>>();
    k_count_deg<<<edgeBlocks, 256>>>(erow);
    k_invdeg<<<nodeBlocks, 256>>>();

    // ---- layer 0: x1 = sage(x) ----
    k_zero_agg<<<zeroBlocks, 256>>>();
    k_scatter<false><<<scatBlocks, 256>>>(x, erow, ecol);
    k_buildB<<<(256 * DD + 255) / 256, 256>>>(Wl0, Wr0);
    k_gemm<false, false><<<gemmBlocks, 256>>>(x, b0, p_x1);

    // ---- layer 1: x2 = sage(relu(x1)) + x1 ----
    k_zero_agg<<<zeroBlocks, 256>>>();
    k_scatter<true><<<scatBlocks, 256>>>(p_x1, erow, ecol);
    k_buildB<<<(256 * DD + 255) / 256, 256>>>(Wl1, Wr1);
    k_gemm<true, true><<<gemmBlocks, 256>>>(p_x1, b1, p_x2);

    // ---- layer 2: out = sage(relu(x2)) + x2 ----
    k_zero_agg<<<zeroBlocks, 256>>>();
    k_scatter<true><<<scatBlocks, 256>>>(p_x2, erow, ecol);
    k_buildB<<<(256 * DD + 255) / 256, 256>>>(Wl2, Wr2);
    k_gemm<true, true><<<gemmBlocks, 256>>>(p_x2, b2, out);
}

// round 2
// speedup vs baseline: 1.2366x; 1.2366x over previous
#include <cuda_runtime.h>

#define NN 50000
#define NE 800000
#define DD 128

// Scratch (static __device__ arrays: allocation-free)
static __device__ float g_agg[(size_t)NN * DD];
static __device__ float g_x1 [(size_t)NN * DD];
static __device__ float g_x2 [(size_t)NN * DD];
static __device__ float g_invdeg[NN];
static __device__ int   g_deg[NN];
static __device__ int   g_rowptr[NN + 1];
static __device__ int   g_cursor[NN];
static __device__ int   g_csr_col[NE];
static __device__ float g_B[256 * DD];   // fused [Wl;Wr] -> [K=256][N=128]

// ---------------- f32x2 helpers ----------------
__device__ __forceinline__ void fma2(unsigned long long& d,
                                     unsigned long long a,
                                     unsigned long long b) {
    asm("fma.rn.f32x2 %0, %1, %2, %0;" : "+l"(d) : "l"(a), "l"(b));
}
__device__ __forceinline__ unsigned long long pack2(float x) {
    unsigned long long r;
    asm("mov.b64 %0, {%1, %1};" : "=l"(r) : "r"(__float_as_uint(x)));
    return r;
}
__device__ __forceinline__ float2 unpack2(unsigned long long v) {
    unsigned int lo, hi;
    asm("mov.b64 {%0, %1}, %2;" : "=r"(lo), "=r"(hi) : "l"(v));
    return make_float2(__uint_as_float(lo), __uint_as_float(hi));
}

// ---------------- degree / CSR build ----------------
__global__ void k_zero_deg() {
    int i = blockIdx.x * blockDim.x + threadIdx.x;
    if (i < NN) g_deg[i] = 0;
}
__global__ void k_count_deg(const int* __restrict__ row) {
    int e = blockIdx.x * blockDim.x + threadIdx.x;
    if (e < NE) atomicAdd(&g_deg[row[e]], 1);
}
__global__ void k_invdeg() {
    int i = blockIdx.x * blockDim.x + threadIdx.x;
    if (i < NN) g_invdeg[i] = 1.0f / fmaxf((float)g_deg[i], 1.0f);
}
// single-block exclusive scan of g_deg -> g_rowptr / g_cursor
__global__ void __launch_bounds__(1024) k_scan() {
    __shared__ int ps[1024];
    const int T = 1024;
    int t = threadIdx.x;
    const int chunk = (NN + T - 1) / T;   // 49
    int beg = t * chunk;
    int end = min(beg + chunk, NN);
    int s = 0;
    for (int i = beg; i < end; i++) s += g_deg[i];
    ps[t] = s;
    __syncthreads();
    // Hillis-Steele inclusive scan
    for (int d = 1; d < T; d <<= 1) {
        int v = (t >= d) ? ps[t - d] : 0;
        __syncthreads();
        ps[t] += v;
        __syncthreads();
    }
    int off = ps[t] - s;   // exclusive prefix for this thread's chunk
    for (int i = beg; i < end; i++) {
        g_rowptr[i] = off;
        g_cursor[i] = off;
        off += g_deg[i];
    }
    if (t == T - 1) g_rowptr[NN] = off;
}
__global__ void k_fill(const int* __restrict__ row, const int* __restrict__ col) {
    int e = blockIdx.x * blockDim.x + threadIdx.x;
    if (e < NE) {
        int r = row[e];
        int p = atomicAdd(&g_cursor[r], 1);
        g_csr_col[p] = col[e];
    }
}

// ---------------- gather aggregation: agg[n] = invdeg[n] * sum_nbr maybe_relu(src[c]) ----------------
// One warp per node; lane owns one float4 (4 feature cols).
template <bool RELU>
__global__ void __launch_bounds__(256) k_gather(const float* __restrict__ src) {
    int w    = (blockIdx.x * blockDim.x + threadIdx.x) >> 5;
    int lane = threadIdx.x & 31;
    if (w >= NN) return;
    int beg = g_rowptr[w];
    int end = g_rowptr[w + 1];
    float4 acc = make_float4(0.f, 0.f, 0.f, 0.f);
    int i = beg;
    for (; i + 1 < end; i += 2) {
        int c0 = __ldg(g_csr_col + i);
        int c1 = __ldg(g_csr_col + i + 1);
        float4 v0 = __ldg((const float4*)(src + (size_t)c0 * DD) + lane);
        float4 v1 = __ldg((const float4*)(src + (size_t)c1 * DD) + lane);
        if (RELU) {
            v0.x = fmaxf(v0.x, 0.f); v0.y = fmaxf(v0.y, 0.f);
            v0.z = fmaxf(v0.z, 0.f); v0.w = fmaxf(v0.w, 0.f);
            v1.x = fmaxf(v1.x, 0.f); v1.y = fmaxf(v1.y, 0.f);
            v1.z = fmaxf(v1.z, 0.f); v1.w = fmaxf(v1.w, 0.f);
        }
        acc.x += v0.x + v1.x; acc.y += v0.y + v1.y;
        acc.z += v0.z + v1.z; acc.w += v0.w + v1.w;
    }
    if (i < end) {
        int c0 = __ldg(g_csr_col + i);
        float4 v0 = __ldg((const float4*)(src + (size_t)c0 * DD) + lane);
        if (RELU) {
            v0.x = fmaxf(v0.x, 0.f); v0.y = fmaxf(v0.y, 0.f);
            v0.z = fmaxf(v0.z, 0.f); v0.w = fmaxf(v0.w, 0.f);
        }
        acc.x += v0.x; acc.y += v0.y; acc.z += v0.z; acc.w += v0.w;
    }
    float s = g_invdeg[w];
    acc.x *= s; acc.y *= s; acc.z *= s; acc.w *= s;
    ((float4*)(g_agg + (size_t)w * DD))[lane] = acc;
}

// ---------------- build fused weight matrix B[k][j] ----------------
__global__ void k_buildB(const float* __restrict__ Wl, const float* __restrict__ Wr) {
    int idx = blockIdx.x * blockDim.x + threadIdx.x;
    if (idx >= 256 * DD) return;
    int k = idx >> 7, j = idx & 127;
    g_B[idx] = (k < 128) ? Wl[j * DD + k] : Wr[j * DD + (k - 128)];
}

// ---------------- fused SAGE GEMM (packed f32x2 FMA) ----------------
// out[i][j] = sum_k A[i][k] * B[k][j] + bias[j] (+ h[i][j] if RES)
//   A[i][k<128]  = g_agg[i][k]         (already mean-scaled)
//   A[i][k>=128] = maybe_relu(h[i][k-128])
template <bool RELU, bool RES>
__global__ void __launch_bounds__(256)
k_gemm(const float* __restrict__ h, const float* __restrict__ bias,
       float* __restrict__ out) {
    __shared__ float As[16 * 132];   // [kk][i], padded stride 132
    __shared__ float Bs[16 * 132];   // [kk][j], padded stride 132
    __shared__ float bsh[128];

    const int t = threadIdx.x;
    const int rowBase = blockIdx.x * 128;
    if (t < 128) bsh[t] = bias[t];
    __syncthreads();

    const int tx = t & 15;   // col group (8 cols = 4 f32x2 pairs)
    const int ty = t >> 4;   // row group

    unsigned long long acc2[8][4];
#pragma unroll
    for (int r = 0; r < 8; r++)
#pragma unroll
        for (int c = 0; c < 4; c++) acc2[r][c] = 0ull;

    for (int k0 = 0; k0 < 256; k0 += 16) {
        // ---- load A tile (transposed into smem) ----
#pragma unroll
        for (int u = 0; u < 2; u++) {
            int cIdx = t + u * 256;            // 0..511
            int i = cIdx >> 2, q = cIdx & 3;   // row-in-tile, float4-within-16k
            int gi = rowBase + i;
            int k = k0 + q * 4;
            float4 v = make_float4(0.f, 0.f, 0.f, 0.f);
            if (gi < NN) {
                if (k0 < 128) {
                    v = __ldg((const float4*)(g_agg + (size_t)gi * DD + k));
                } else {
                    v = __ldg((const float4*)(h + (size_t)gi * DD + (k - 128)));
                    if (RELU) {
                        v.x = fmaxf(v.x, 0.f); v.y = fmaxf(v.y, 0.f);
                        v.z = fmaxf(v.z, 0.f); v.w = fmaxf(v.w, 0.f);
                    }
                }
            }
            As[(q * 4 + 0) * 132 + i] = v.x;
            As[(q * 4 + 1) * 132 + i] = v.y;
            As[(q * 4 + 2) * 132 + i] = v.z;
            As[(q * 4 + 3) * 132 + i] = v.w;
        }
        // ---- load B tile ----
#pragma unroll
        for (int u = 0; u < 2; u++) {
            int cIdx = t + u * 256;            // 0..511
            int kk = cIdx >> 5, f = cIdx & 31; // 16 rows x 32 float4
            float4 v = __ldg((const float4*)(g_B + (k0 + kk) * DD + f * 4));
            *(float4*)(Bs + kk * 132 + f * 4) = v;
        }
        __syncthreads();

        // ---- compute: 32 FFMA2 per kk ----
#pragma unroll
        for (int kk = 0; kk < 16; kk++) {
            float a[8];
            *(float4*)(a)     = *(const float4*)(As + kk * 132 + ty * 8);
            *(float4*)(a + 4) = *(const float4*)(As + kk * 132 + ty * 8 + 4);
            ulonglong2 bA = *(const ulonglong2*)(Bs + kk * 132 + tx * 8);
            ulonglong2 bB = *(const ulonglong2*)(Bs + kk * 132 + tx * 8 + 4);
            unsigned long long b2[4] = {bA.x, bA.y, bB.x, bB.y};
#pragma unroll
            for (int r = 0; r < 8; r++) {
                unsigned long long ar = pack2(a[r]);
#pragma unroll
                for (int c = 0; c < 4; c++) fma2(acc2[r][c], ar, b2[c]);
            }
        }
        __syncthreads();
    }

    // ---- epilogue: bias (+ residual), store ----
#pragma unroll
    for (int r = 0; r < 8; r++) {
        int gi = rowBase + ty * 8 + r;
        if (gi >= NN) continue;
        float o[8];
#pragma unroll
        for (int c = 0; c < 4; c++) {
            float2 p = unpack2(acc2[r][c]);
            o[2 * c]     = p.x;
            o[2 * c + 1] = p.y;
        }
#pragma unroll
        for (int c = 0; c < 8; c += 4) {
            int j = tx * 8 + c;
            float4 ov;
            ov.x = o[c]     + bsh[j];
            ov.y = o[c + 1] + bsh[j + 1];
            ov.z = o[c + 2] + bsh[j + 2];
            ov.w = o[c + 3] + bsh[j + 3];
            if (RES) {
                float4 xv = __ldg((const float4*)(h + (size_t)gi * DD + j));
                ov.x += xv.x; ov.y += xv.y; ov.z += xv.z; ov.w += xv.w;
            }
            *(float4*)(out + (size_t)gi * DD + j) = ov;
        }
    }
}

// ---------------- launch ----------------
extern "C" void kernel_launch(void* const* d_in, const int* in_sizes, int n_in,
                              void* d_out, int out_size) {
    const float* x    = (const float*)d_in[0];
    const int*   erow = (const int*)  d_in[1];
    const int*   ecol = (const int*)  d_in[2];
    const float* Wl0 = (const float*)d_in[3];
    const float* Wr0 = (const float*)d_in[4];
    const float* b0  = (const float*)d_in[5];
    const float* Wl1 = (const float*)d_in[6];
    const float* Wr1 = (const float*)d_in[7];
    const float* b1  = (const float*)d_in[8];
    const float* Wl2 = (const float*)d_in[9];
    const float* Wr2 = (const float*)d_in[10];
    const float* b2  = (const float*)d_in[11];
    float* out = (float*)d_out;

    float *p_x1 = nullptr, *p_x2 = nullptr;
    cudaGetSymbolAddress((void**)&p_x1, g_x1);
    cudaGetSymbolAddress((void**)&p_x2, g_x2);

    const int nodeBlocks   = (NN + 255) / 256;
    const int edgeBlocks   = (NE + 255) / 256;
    const int gatherBlocks = (NN * 32 + 255) / 256;   // 6250
    const int gemmBlocks   = (NN + 127) / 128;        // 391

    // CSR build (per call; graph replays everything)
    k_zero_deg<<<nodeBlocks, 256>>>();
    k_count_deg<<<edgeBlocks, 256>>>(erow);
    k_scan<<<1, 1024>>>();
    k_fill<<<edgeBlocks, 256>>>(erow, ecol);
    k_invdeg<<<nodeBlocks, 256>>>();

    // ---- layer 0: x1 = sage(x) ----
    k_gather<false><<<gatherBlocks, 256>>>(x);
    k_buildB<<<(256 * DD + 255) / 256, 256>>>(Wl0, Wr0);
    k_gemm<false, false><<<gemmBlocks, 256>>>(x, b0, p_x1);

    // ---- layer 1: x2 = sage(relu(x1)) + x1 ----
    k_gather<true><<<gatherBlocks, 256>>>(p_x1);
    k_buildB<<<(256 * DD + 255) / 256, 256>>>(Wl1, Wr1);
    k_gemm<true, true><<<gemmBlocks, 256>>>(p_x1, b1, p_x2);

    // ---- layer 2: out = sage(relu(x2)) + x2 ----
    k_gather<true><<<gatherBlocks, 256>>>(p_x2);
    k_buildB<<<(256 * DD + 255) / 256, 256>>>(Wl2, Wr2);
    k_gemm<true, true><<<gemmBlocks, 256>>>(p_x2, b2, out);
}

// round 4
// speedup vs baseline: 1.4418x; 1.1659x over previous
#include <cuda_runtime.h>
#include <cuda_bf16.h>
#include <cstdint>

#define NN 50000
#define NE 800000
#define DD 128

// Scratch (static __device__ arrays: allocation-free)
static __device__ float g_agg[(size_t)NN * DD];
static __device__ float g_x1 [(size_t)NN * DD];
static __device__ float g_x2 [(size_t)NN * DD];
static __device__ float g_invdeg[NN];
static __device__ int   g_deg[NN];
static __device__ int   g_rowptr[NN + 1];
static __device__ int   g_cursor[NN];
static __device__ int   g_csr_col[NE];

// ---------------- degree / CSR build ----------------
__global__ void k_zero_deg() {
    int i = blockIdx.x * blockDim.x + threadIdx.x;
    if (i < NN) g_deg[i] = 0;
}
__global__ void k_count_deg(const int* __restrict__ row) {
    int e = blockIdx.x * blockDim.x + threadIdx.x;
    if (e < NE) atomicAdd(&g_deg[row[e]], 1);
}
__global__ void __launch_bounds__(1024) k_scan() {
    __shared__ int ps[1024];
    const int T = 1024;
    int t = threadIdx.x;
    const int chunk = (NN + T - 1) / T;
    int beg = t * chunk;
    int end = min(beg + chunk, NN);
    int s = 0;
    for (int i = beg; i < end; i++) s += g_deg[i];
    ps[t] = s;
    __syncthreads();
    for (int d = 1; d < T; d <<= 1) {
        int v = (t >= d) ? ps[t - d] : 0;
        __syncthreads();
        ps[t] += v;
        __syncthreads();
    }
    int off = ps[t] - s;
    for (int i = beg; i < end; i++) {
        int dg = g_deg[i];
        g_rowptr[i] = off;
        g_cursor[i] = off;
        g_invdeg[i] = 1.0f / fmaxf((float)dg, 1.0f);
        off += dg;
    }
    if (t == T - 1) g_rowptr[NN] = off;
}
__global__ void k_fill(const int* __restrict__ row, const int* __restrict__ col) {
    int e = blockIdx.x * blockDim.x + threadIdx.x;
    if (e < NE) {
        int r = row[e];
        int p = atomicAdd(&g_cursor[r], 1);
        g_csr_col[p] = col[e];
    }
}

// ---------------- gather: agg[n] = invdeg[n] * sum_nbr maybe_relu(src[c]) ----------------
template <bool RELU>
__global__ void __launch_bounds__(256) k_gather(const float* __restrict__ src) {
    int w    = (blockIdx.x * blockDim.x + threadIdx.x) >> 5;
    int lane = threadIdx.x & 31;
    if (w >= NN) return;
    int beg = g_rowptr[w];
    int end = g_rowptr[w + 1];
    float4 acc = make_float4(0.f, 0.f, 0.f, 0.f);
    int i = beg;
    for (; i + 1 < end; i += 2) {
        int c0 = __ldg(g_csr_col + i);
        int c1 = __ldg(g_csr_col + i + 1);
        float4 v0 = __ldg((const float4*)(src + (size_t)c0 * DD) + lane);
        float4 v1 = __ldg((const float4*)(src + (size_t)c1 * DD) + lane);
        if (RELU) {
            v0.x = fmaxf(v0.x, 0.f); v0.y = fmaxf(v0.y, 0.f);
            v0.z = fmaxf(v0.z, 0.f); v0.w = fmaxf(v0.w, 0.f);
            v1.x = fmaxf(v1.x, 0.f); v1.y = fmaxf(v1.y, 0.f);
            v1.z = fmaxf(v1.z, 0.f); v1.w = fmaxf(v1.w, 0.f);
        }
        acc.x += v0.x + v1.x; acc.y += v0.y + v1.y;
        acc.z += v0.z + v1.z; acc.w += v0.w + v1.w;
    }
    if (i < end) {
        int c0 = __ldg(g_csr_col + i);
        float4 v0 = __ldg((const float4*)(src + (size_t)c0 * DD) + lane);
        if (RELU) {
            v0.x = fmaxf(v0.x, 0.f); v0.y = fmaxf(v0.y, 0.f);
            v0.z = fmaxf(v0.z, 0.f); v0.w = fmaxf(v0.w, 0.f);
        }
        acc.x += v0.x; acc.y += v0.y; acc.z += v0.z; acc.w += v0.w;
    }
    float s = g_invdeg[w];
    acc.x *= s; acc.y *= s; acc.z *= s; acc.w *= s;
    ((float4*)(g_agg + (size_t)w * DD))[lane] = acc;
}

// ================= mma.sync bf16-split GEMM =================
// out[i][j] = sum_k A[i][k]*B[j][k] + bias[j] (+ h[i][j] if RES)
//   A[i][k<128]  = g_agg[i][k] ;  A[i][k>=128] = maybe_relu(h[i][k-128])
//   B[j][k<128]  = Wl[j][k]    ;  B[j][k>=128] = Wr[j][k-128]   (K-major already)
// Split v = hi(bf16) + lo(bf16); D = AhiBhi + AhiBlo + AloBhi   (err ~1e-5)
// K chunked by 64; planes: 128 rows x 64 bf16 (128B rows, SW128 XOR swizzle).

#define OFF_BIAS 0
#define OFF_AHI  1024
#define OFF_ALO  (1024 + 16384)
#define OFF_BHI  (1024 + 32768)
#define OFF_BLO  (1024 + 49152)
#define SMEM_GEMM (1024 + 65536)

__device__ __forceinline__ uint32_t s2u(const void* p) {
    uint32_t a;
    asm("{ .reg .u64 t; cvta.to.shared.u64 t, %1; cvt.u32.u64 %0, t; }" : "=r"(a) : "l"(p));
    return a;
}
__device__ __forceinline__ void ldsm4(uint32_t& r0, uint32_t& r1, uint32_t& r2, uint32_t& r3,
                                      uint32_t addr) {
    asm volatile("ldmatrix.sync.aligned.m8n8.x4.shared.b16 {%0,%1,%2,%3}, [%4];"
                 : "=r"(r0), "=r"(r1), "=r"(r2), "=r"(r3) : "r"(addr));
}
__device__ __forceinline__ void mma16816(float* d, const uint32_t* a, const uint32_t* b) {
    asm volatile("mma.sync.aligned.m16n8k16.row.col.f32.bf16.bf16.f32 "
                 "{%0,%1,%2,%3}, {%4,%5,%6,%7}, {%8,%9}, {%0,%1,%2,%3};"
                 : "+f"(d[0]), "+f"(d[1]), "+f"(d[2]), "+f"(d[3])
                 : "r"(a[0]), "r"(a[1]), "r"(a[2]), "r"(a[3]), "r"(b[0]), "r"(b[1]));
}
// per-lane ldmatrix address for a 16(row)x16(k) tile at (r0,k0) in a swizzled plane
__device__ __forceinline__ uint32_t tile_addr(uint32_t planeBase, int lane, int r0, int k0) {
    int rr = r0 + (lane & 15);
    int kk = k0 + ((lane >> 4) << 3);
    uint32_t off = rr * 128 + kk * 2;
    return planeBase + (off ^ ((off >> 3) & 0x70));
}
// split one float4 into bf16 hi/lo planes (8B each), swizzled store
__device__ __forceinline__ void st_hl(char* hiBase, char* loBase, int row, int q, float4 v) {
    __nv_bfloat16 hx = __float2bfloat16_rn(v.x);
    __nv_bfloat16 hy = __float2bfloat16_rn(v.y);
    __nv_bfloat16 hz = __float2bfloat16_rn(v.z);
    __nv_bfloat16 hw = __float2bfloat16_rn(v.w);
    __nv_bfloat16 lx = __float2bfloat16_rn(v.x - __bfloat162float(hx));
    __nv_bfloat16 ly = __float2bfloat16_rn(v.y - __bfloat162float(hy));
    __nv_bfloat16 lz = __float2bfloat16_rn(v.z - __bfloat162float(hz));
    __nv_bfloat16 lw = __float2bfloat16_rn(v.w - __bfloat162float(hw));
    __nv_bfloat162 H01, H23, L01, L23;
    H01.x = hx; H01.y = hy; H23.x = hz; H23.y = hw;
    L01.x = lx; L01.y = ly; L23.x = lz; L23.y = lw;
    int off = row * 128 + q * 8;
    int sw = off ^ ((off >> 3) & 0x70);
    uint2 Hw, Lw;
    Hw.x = *(uint32_t*)&H01; Hw.y = *(uint32_t*)&H23;
    Lw.x = *(uint32_t*)&L01; Lw.y = *(uint32_t*)&L23;
    *(uint2*)(hiBase + sw) = Hw;
    *(uint2*)(loBase + sw) = Lw;
}

template <bool RELU, bool RES>
__global__ void __launch_bounds__(256)
k_gemm_mma(const float* __restrict__ h, const float* __restrict__ Wl,
           const float* __restrict__ Wr, const float* __restrict__ bias,
           float* __restrict__ out)
{
    extern __shared__ char smem[];
    const uint32_t sb = s2u(smem);
    const int t    = threadIdx.x;
    const int wid  = t >> 5;
    const int lane = t & 31;
    const int rowBase = blockIdx.x * 128;
    const int wm = (wid >> 2) * 64;   // warp m-base (0 or 64)
    const int wn = (wid & 3) * 32;    // warp n-base (0,32,64,96)

    if (t < 128) ((float*)(smem + OFF_BIAS))[t] = bias[t];

    float acc[4][4][4];   // [mtile][ntile][4]
#pragma unroll
    for (int i = 0; i < 4; i++)
#pragma unroll
        for (int j = 0; j < 4; j++)
#pragma unroll
            for (int q = 0; q < 4; q++) acc[i][j][q] = 0.f;

    for (int c = 0; c < 4; c++) {
        if (c > 0) __syncthreads();   // previous compute done before refill
        // ---- fill chunk c (K = [c*64, c*64+64)) ----
#pragma unroll
        for (int u = 0; u < 8; u++) {
            int idx = t + u * 256;        // 0..2047 float4 slots (128 rows x 16)
            int row = idx >> 4;
            int q   = idx & 15;
            int gi  = rowBase + row;
            float4 va = make_float4(0.f, 0.f, 0.f, 0.f);
            if (gi < NN) {
                if (c < 2) {
                    va = __ldg((const float4*)(g_agg + (size_t)gi * DD + c * 64) + q);
                } else {
                    va = __ldg((const float4*)(h + (size_t)gi * DD + (c - 2) * 64) + q);
                    if (RELU) {
                        va.x = fmaxf(va.x, 0.f); va.y = fmaxf(va.y, 0.f);
                        va.z = fmaxf(va.z, 0.f); va.w = fmaxf(va.w, 0.f);
                    }
                }
            }
            st_hl(smem + OFF_AHI, smem + OFF_ALO, row, q, va);
            const float* W = (c < 2) ? Wl : Wr;
            float4 vb = __ldg((const float4*)(W + (size_t)row * DD + (c & 1) * 64) + q);
            st_hl(smem + OFF_BHI, smem + OFF_BLO, row, q, vb);
        }
        __syncthreads();

        // ---- compute: 4 k-steps of 16 ----
#pragma unroll
        for (int ks = 0; ks < 4; ks++) {
            const int k0 = ks * 16;
            // B fragments: 2 ldsm4 per plane cover all 4 n-tiles (n=wn..wn+31)
            uint32_t bhi[4][2], blo[4][2];
#pragma unroll
            for (int p = 0; p < 2; p++) {
                uint32_t r0, r1, r2, r3;
                ldsm4(r0, r1, r2, r3, tile_addr(sb + OFF_BHI, lane, wn + p * 16, k0));
                bhi[2 * p][0] = r0;     bhi[2 * p][1] = r2;
                bhi[2 * p + 1][0] = r1; bhi[2 * p + 1][1] = r3;
                ldsm4(r0, r1, r2, r3, tile_addr(sb + OFF_BLO, lane, wn + p * 16, k0));
                blo[2 * p][0] = r0;     blo[2 * p][1] = r2;
                blo[2 * p + 1][0] = r1; blo[2 * p + 1][1] = r3;
            }
#pragma unroll
            for (int i = 0; i < 4; i++) {
                uint32_t ahi[4], alo[4];
                ldsm4(ahi[0], ahi[1], ahi[2], ahi[3],
                      tile_addr(sb + OFF_AHI, lane, wm + i * 16, k0));
                ldsm4(alo[0], alo[1], alo[2], alo[3],
                      tile_addr(sb + OFF_ALO, lane, wm + i * 16, k0));
#pragma unroll
                for (int j = 0; j < 4; j++) {
                    mma16816(acc[i][j], ahi, bhi[j]);
                    mma16816(acc[i][j], ahi, blo[j]);
                    mma16816(acc[i][j], alo, bhi[j]);
                }
            }
        }
    }

    // ---- epilogue: bias (+ residual), direct register->gmem ----
    const float* bsh = (const float*)(smem + OFF_BIAS);
    const int tr = lane >> 2;         // 0..7
    const int tc = (lane & 3) * 2;    // 0,2,4,6
#pragma unroll
    for (int i = 0; i < 4; i++) {
#pragma unroll
        for (int half = 0; half < 2; half++) {
            int gi = rowBase + wm + i * 16 + tr + half * 8;
            if (gi >= NN) continue;
#pragma unroll
            for (int j = 0; j < 4; j++) {
                int col = wn + j * 8 + tc;
                float2 o;
                o.x = acc[i][j][half * 2]     + bsh[col];
                o.y = acc[i][j][half * 2 + 1] + bsh[col + 1];
                if (RES) {
                    float2 rv = __ldg((const float2*)(h + (size_t)gi * DD + col));
                    o.x += rv.x; o.y += rv.y;
                }
                *(float2*)(out + (size_t)gi * DD + col) = o;
            }
        }
    }
}

// ---------------- launch ----------------
extern "C" void kernel_launch(void* const* d_in, const int* in_sizes, int n_in,
                              void* d_out, int out_size) {
    const float* x    = (const float*)d_in[0];
    const int*   erow = (const int*)  d_in[1];
    const int*   ecol = (const int*)  d_in[2];
    const float* Wl0 = (const float*)d_in[3];
    const float* Wr0 = (const float*)d_in[4];
    const float* b0  = (const float*)d_in[5];
    const float* Wl1 = (const float*)d_in[6];
    const float* Wr1 = (const float*)d_in[7];
    const float* b1  = (const float*)d_in[8];
    const float* Wl2 = (const float*)d_in[9];
    const float* Wr2 = (const float*)d_in[10];
    const float* b2  = (const float*)d_in[11];
    float* out = (float*)d_out;

    float *p_x1 = nullptr, *p_x2 = nullptr;
    cudaGetSymbolAddress((void**)&p_x1, g_x1);
    cudaGetSymbolAddress((void**)&p_x2, g_x2);

    cudaFuncSetAttribute(k_gemm_mma<false, false>,
                         cudaFuncAttributeMaxDynamicSharedMemorySize, SMEM_GEMM);
    cudaFuncSetAttribute(k_gemm_mma<true, true>,
                         cudaFuncAttributeMaxDynamicSharedMemorySize, SMEM_GEMM);

    const int nodeBlocks   = (NN + 255) / 256;
    const int edgeBlocks   = (NE + 255) / 256;
    const int gatherBlocks = (NN * 32 + 255) / 256;   // 6250
    const int gemmBlocks   = (NN + 127) / 128;        // 391

    // CSR build
    k_zero_deg<<<nodeBlocks, 256>>>();
    k_count_deg<<<edgeBlocks, 256>>>(erow);
    k_scan<<<1, 1024>>>();
    k_fill<<<edgeBlocks, 256>>>(erow, ecol);

    // ---- layer 0: x1 = sage(x) ----
    k_gather<false><<<gatherBlocks, 256>>>(x);
    k_gemm_mma<false, false><<<gemmBlocks, 256, SMEM_GEMM>>>(x, Wl0, Wr0, b0, p_x1);

    // ---- layer 1: x2 = sage(relu(x1)) + x1 ----
    k_gather<true><<<gatherBlocks, 256>>>(p_x1);
    k_gemm_mma<true, true><<<gemmBlocks, 256, SMEM_GEMM>>>(p_x1, Wl1, Wr1, b1, p_x2);

    // ---- layer 2: out = sage(relu(x2)) + x2 ----
    k_gather<true><<<gatherBlocks, 256>>>(p_x2);
    k_gemm_mma<true, true><<<gemmBlocks, 256, SMEM_GEMM>>>(p_x2, Wl2, Wr2, b2, out);
}